// round 10
// baseline (speedup 1.0000x reference)
#include <cuda_runtime.h>

// GRU4Rec user module: ragged GRU(128) -> dense(128) -> L2 normalize.
// Inputs: x f32[T,128], offset i32[B] (i64 auto-detect), W_ih f32[384,128],
//         W_hh f32[384,128], W_dense f32[128,128], b_dense f32[128]
// Output: f32[B,128]
//
// R10 = proven R7 base + minimal deltas:
//  - k_rec identical to R7 (passed, 1928us)
//  - k_xproj: 8-token tiles, 1 acc chain/token, j-loop unroll capped at 8
//  - launch order xproj -> sort -> rec (ncu sampling lands on heavy kernel)

#define DIMD 128
#define DIMH 128
#define G3   384
#define MAXB 4096
#define MAXLEN 200

__device__ float g_xproj[(size_t)2048 * MAXLEN * G3];
__device__ int g_off[MAXB];
__device__ int g_len[MAXB];
__device__ int g_order[MAXB];

__device__ __forceinline__ void ffma2(unsigned long long &acc,
                                      unsigned long long a,
                                      unsigned long long b) {
    asm("fma.rn.f32x2 %0, %1, %2, %0;" : "+l"(acc) : "l"(a), "l"(b));
}
__device__ __forceinline__ float f2lo(unsigned long long v) {
    return __uint_as_float((unsigned int)v);
}
__device__ __forceinline__ float f2hi(unsigned long long v) {
    return __uint_as_float((unsigned int)(v >> 32));
}
__device__ __forceinline__ float fast_tanh(float v) {
    float av = fabsf(v);
    float e = __expf(-2.0f * av);
    float m = (1.0f - e) * __frcp_rn(1.0f + e);
    return copysignf(m, v);
}
__device__ __forceinline__ float fast_sigmoid(float v) {
    return __frcp_rn(1.0f + __expf(-v));
}
__device__ __forceinline__ int load_off(const void* p, int i, bool is64) {
    return is64 ? (int)((const long long*)p)[i] : ((const int*)p)[i];
}

// ---------------------------------------------------------------------------
// K0: offsets/lengths + counting sort of sequence indices by length.
// ---------------------------------------------------------------------------
__global__ void k_sort(const void* __restrict__ off_raw, int T, int B) {
    __shared__ int s_cnt[MAXLEN + 1];
    const int tid = threadIdx.x;
    const bool is64 = (B > 1) && (((const int*)off_raw)[1] == 0);

    for (int i = tid; i <= MAXLEN; i += blockDim.x) s_cnt[i] = 0;
    __syncthreads();

    for (int i = tid; i < B; i += blockDim.x) {
        int o  = load_off(off_raw, i, is64);
        int oe = (i + 1 < B) ? load_off(off_raw, i + 1, is64) : T;
        int l = oe - o;
        if (o < 0) o = 0;
        if (l < 0) l = 0;
        if (l > MAXLEN) l = MAXLEN;
        g_off[i] = o;
        g_len[i] = l;
        atomicAdd(&s_cnt[l], 1);
    }
    __syncthreads();

    if (tid == 0) {
        int run = 0;
        for (int j = 0; j <= MAXLEN; j++) { int c = s_cnt[j]; s_cnt[j] = run; run += c; }
    }
    __syncthreads();

    for (int i = tid; i < B; i += blockDim.x) {
        int pos = atomicAdd(&s_cnt[g_len[i]], 1);
        g_order[pos] = i;
    }
}

// ---------------------------------------------------------------------------
// K1: x_proj = x @ W_ih^T. 8-token tiles, double-buffered, 1 barrier/tile.
// One accumulator chain per token (8 independent chains). j-loop unroll
// capped at 8 to keep the compiled body small.
// ---------------------------------------------------------------------------
__global__ __launch_bounds__(384, 1)
void k_xproj(const float* __restrict__ x,
             const float* __restrict__ W_ih,
             int T, int chunk) {
    const int g = threadIdx.x;

    int t0 = blockIdx.x * chunk;
    int t1 = min(T, t0 + chunk);
    if (t0 >= t1) return;  // uniform across block

    unsigned long long Wr[64];
    {
        const unsigned long long* Wp =
            (const unsigned long long*)(W_ih + (size_t)g * DIMD);
        #pragma unroll
        for (int j = 0; j < 64; j++) Wr[j] = Wp[j];
    }

    __shared__ __align__(16) float sx[2][8][DIMD];

    // prologue: load tile 0 (threads 0..255: token g/32, float4 g%32)
    if (g < 256) {
        int tk = t0 + (g >> 5);
        if (tk < t1)
            ((float4*)sx[0][g >> 5])[g & 31] =
                ((const float4*)x)[(size_t)tk * 32 + (g & 31)];
    }
    __syncthreads();

    int buf = 0;
    for (int ts = t0; ts < t1; ts += 8) {
        // prefetch next tile into other buffer
        if (g < 256) {
            int tk = ts + 8 + (g >> 5);
            if (tk < t1)
                ((float4*)sx[buf ^ 1][g >> 5])[g & 31] =
                    ((const float4*)x)[(size_t)tk * 32 + (g & 31)];
        }

        unsigned long long acc[8];
        #pragma unroll
        for (int k = 0; k < 8; k++) acc[k] = 0ull;

        #pragma unroll 8
        for (int j = 0; j < 32; j++) {
            unsigned long long w0 = Wr[2 * j], w1 = Wr[2 * j + 1];
            #pragma unroll
            for (int k = 0; k < 8; k++) {
                ulonglong2 v = ((const ulonglong2*)sx[buf][k])[j];
                ffma2(acc[k], w0, v.x);
                ffma2(acc[k], w1, v.y);
            }
        }
        #pragma unroll
        for (int k = 0; k < 8; k++) {
            int tk = ts + k;
            if (tk < t1) {
                float s = f2lo(acc[k]) + f2hi(acc[k]);
                g_xproj[(size_t)tk * G3 + g] = s;
            }
        }

        __syncthreads();
        buf ^= 1;
    }
}

// ---------------------------------------------------------------------------
// K2: GRU recurrence, 2 length-sorted sequences per block (384 threads).
// Identical to R7 (proven). Thread g owns W_hh row g in registers.
// ---------------------------------------------------------------------------
__global__ __launch_bounds__(384, 1)
void k_rec(const float* __restrict__ W_hh,
           const float* __restrict__ W_dense,
           const float* __restrict__ b_dense,
           float* __restrict__ out,
           int B) {
    const int g = threadIdx.x;

    const int i0 = 2 * blockIdx.x;
    const int seq0 = g_order[i0];
    const int seq1 = (i0 + 1 < B) ? g_order[i0 + 1] : -1;

    const int o0 = g_off[seq0];
    const int len0 = g_len[seq0];
    const int o1 = (seq1 >= 0) ? g_off[seq1] : 0;
    const int len1 = (seq1 >= 0) ? g_len[seq1] : 0;
    const int lmax = max(len0, len1);

    unsigned long long Wr[64];
    {
        const unsigned long long* Wp =
            (const unsigned long long*)(W_hh + (size_t)g * DIMH);
        #pragma unroll
        for (int j = 0; j < 64; j++) Wr[j] = Wp[j];
    }

    __shared__ __align__(16) float sh_h[2][DIMH];
    __shared__ float sh_pre[2][G3];
    __shared__ float sh_xgn[2][DIMH];
    __shared__ float sred[8];

    if (g < DIMH) { sh_h[0][g] = 0.0f; sh_h[1][g] = 0.0f; }
    __syncthreads();

    const float* xg0 = g_xproj + (size_t)o0 * G3 + g;
    const float* xg1 = g_xproj + (size_t)o1 * G3 + g;

    float xv0 = (0 < len0) ? xg0[0] : 0.0f;
    float xv1 = (0 < len1) ? xg1[0] : 0.0f;

    for (int t = 0; t < lmax; t++) {
        float xn0 = (t + 1 < len0) ? xg0[(size_t)(t + 1) * G3] : 0.0f;
        float xn1 = (t + 1 < len1) ? xg1[(size_t)(t + 1) * G3] : 0.0f;

        unsigned long long a00 = 0ull, a01 = 0ull, a10 = 0ull, a11 = 0ull;
        const ulonglong2* hp0 = (const ulonglong2*)sh_h[0];
        const ulonglong2* hp1 = (const ulonglong2*)sh_h[1];
        #pragma unroll
        for (int j = 0; j < 32; j++) {
            ulonglong2 v0 = hp0[j];            // broadcast LDS.128
            ulonglong2 v1 = hp1[j];
            ffma2(a00, Wr[2 * j],     v0.x);
            ffma2(a01, Wr[2 * j + 1], v0.y);
            ffma2(a10, Wr[2 * j],     v1.x);
            ffma2(a11, Wr[2 * j + 1], v1.y);
        }
        float hg0 = (f2lo(a00) + f2hi(a00)) + (f2lo(a01) + f2hi(a01));
        float hg1 = (f2lo(a10) + f2hi(a10)) + (f2lo(a11) + f2hi(a11));

        if (g < 2 * DIMH) {
            sh_pre[0][g] = hg0 + xv0;          // r,z pre-activations
            sh_pre[1][g] = hg1 + xv1;
        } else {
            sh_pre[0][g] = hg0;                // n: hg kept separate
            sh_pre[1][g] = hg1;
            sh_xgn[0][g - 2 * DIMH] = xv0;
            sh_xgn[1][g - 2 * DIMH] = xv1;
        }
        __syncthreads();

        if (g < 2 * DIMH) {                    // warps 0..7: gate math, 2 seqs
            int s = g >> 7;                    // uniform per warp
            int j = g & (DIMH - 1);
            int ls = s ? len1 : len0;
            if (t < ls) {
                float r = fast_sigmoid(sh_pre[s][j]);
                float z = fast_sigmoid(sh_pre[s][DIMH + j]);
                float n = fast_tanh(fmaf(r, sh_pre[s][2 * DIMH + j], sh_xgn[s][j]));
                float h_old = sh_h[s][j];
                sh_h[s][j] = fmaf(z, h_old - n, n);
            }
        }
        __syncthreads();

        xv0 = xn0; xv1 = xn1;
    }

    // dense + L2 normalize: threads 0..255 (s = g>>7, d = g&127)
    float val = 0.0f;
    const int s = g >> 7;
    const int d = g & (DIMH - 1);
    if (g < 2 * DIMH) {
        unsigned long long a0 = 0ull, a1 = 0ull;
        const unsigned long long* Wd =
            (const unsigned long long*)(W_dense + (size_t)d * DIMH);
        const ulonglong2* hp = (const ulonglong2*)sh_h[s];
        #pragma unroll
        for (int j = 0; j < 32; j++) {
            ulonglong2 hv = hp[j];
            ffma2(a0, Wd[2 * j],     hv.x);
            ffma2(a1, Wd[2 * j + 1], hv.y);
        }
        val = (f2lo(a0) + f2hi(a0)) + (f2lo(a1) + f2hi(a1)) + b_dense[d];

        float ss = val * val;
        #pragma unroll
        for (int sh = 16; sh > 0; sh >>= 1)
            ss += __shfl_xor_sync(0xffffffffu, ss, sh);
        if ((g & 31) == 0) sred[g >> 5] = ss;   // warps 0..7
    }
    __syncthreads();

    if (g < 2 * DIMH) {
        int base = s * 4;
        float ss = sred[base] + sred[base + 1] + sred[base + 2] + sred[base + 3];
        float nrm = fmaxf(sqrtf(ss), 1e-12f);
        int seq = s ? seq1 : seq0;
        if (seq >= 0)
            out[(size_t)seq * DIMD + d] = val / nrm;
    }
}

// ---------------------------------------------------------------------------
extern "C" void kernel_launch(void* const* d_in, const int* in_sizes, int n_in,
                              void* d_out, int out_size) {
    const float* x       = (const float*)d_in[0];
    const void*  off     = d_in[1];                   // int32 or int64
    const float* W_ih    = (const float*)d_in[2];
    const float* W_hh    = (const float*)d_in[3];
    const float* W_dense = (const float*)d_in[4];
    const float* b_dense = (const float*)d_in[5];
    float*       out     = (float*)d_out;

    const int T = in_sizes[0] / DIMD;   // total tokens
    const int B = out_size / DIMD;      // number of sequences

    const int G1 = 1184;                // 8 waves at 1 block/SM on 148 SMs
    const int chunk = (T + G1 - 1) / G1;
    k_xproj<<<G1, 384>>>(x, W_ih, T, chunk);   // first: ncu sampling target

    k_sort<<<1, 256>>>(off, T, B);             // only needed before k_rec

    const int G2 = (B + 1) / 2;
    k_rec<<<G2, 384>>>(W_hh, W_dense, b_dense, out, B);
}